// round 12
// baseline (speedup 1.0000x reference)
#include <cuda_runtime.h>
#include <cstdint>

// QuantumParity analytic reduction (derived R1):
//   The circuit's features are Heisenberg-evolved parity expectations of a
//   product state; every feature is a contiguous-range cosine product:
//     feat_k     = prod_{q=0..k}   cos(x_q)
//     feat_(i,j) = prod_{q=i+1..j} cos(x_q)
//   out[c] = b[c] + sum_f W[c][f] * feat_f
//
// R12 (terminal): R9 structure — Horner-factored packed f32x2 dot (exactly
// 37 fma2 + 37 LDS.64), scalar degree-9 cos, smem W fetched in flight under
// the cos math, one barrier, single kernel node, block 256 — plus the
// predicate-free fast path when grid divides nrows exactly. Default cache
// policy (.cs hints regressed in R11).
//
// The kernel sits at a small-transfer floor: 5.25MB compulsory-miss traffic,
// nothing on-chip above 14% utilization; duration = launch ramp + cold DRAM
// latency. Measured band 5.2-5.5us kernel / ~6.6us bench across all variants.

#define NQ 8
#define NFEAT 36
#define BLOCK 256

__device__ __forceinline__ uint64_t pack2(float lo, float hi) {
    uint64_t r;
    asm("mov.b64 %0, {%1, %2};" : "=l"(r) : "f"(lo), "f"(hi));
    return r;
}
__device__ __forceinline__ uint64_t pack_dup(float v) {
    uint64_t r;
    asm("mov.b64 %0, {%1, %1};" : "=l"(r) : "f"(v));
    return r;
}
__device__ __forceinline__ uint64_t fma2(uint64_t a, uint64_t b, uint64_t c) {
    uint64_t d;
    asm("fma.rn.f32x2 %0, %1, %2, %3;" : "=l"(d) : "l"(a), "l"(b), "l"(c));
    return d;
}
__device__ __forceinline__ uint64_t add2(uint64_t a, uint64_t b) {
    uint64_t d;
    asm("add.rn.f32x2 %0, %1, %2;" : "=l"(d) : "l"(a), "l"(b));
    return d;
}
__device__ __forceinline__ uint64_t lds64(uint32_t addr) {
    uint64_t d;
    asm("ld.shared.b64 %0, [%1];" : "=l"(d) : "r"(addr));
    return d;
}

__device__ __forceinline__ float cos_poly(float x) {
    // x in [0, pi]; cos(x) = -sin(x - pi/2). Degree-9 Taylor, |err| < 2.8e-6.
    float t = x - 1.57079632679489662f;
    float u = t * t;
    float p = fmaf(u, 2.75573192e-6f, -1.98412698e-4f);
    p = fmaf(u, p, 8.33333333e-3f);
    p = fmaf(u, p, -1.66666667e-1f);
    p = fmaf(u, p, 1.0f);
    return -t * p;
}

// Shared body. GUARDED=false: row is known in-range, no predicates anywhere.
template <bool GUARDED>
__device__ __forceinline__ void body(const float* __restrict__ x,
                                     const float* __restrict__ W,
                                     const float* __restrict__ bias,
                                     float* __restrict__ out,
                                     int nrows) {
    __shared__ uint64_t sW[NFEAT + 1];  // sW[f] = {W0[f], W1[f]}; sW[36] = bias
    int tid = threadIdx.x;
    int row = blockIdx.x * BLOCK + tid;
    int rl = GUARDED ? (row < nrows ? row : (nrows - 1)) : row;

    // x load first: DRAM latency starts immediately.
    const float4* xp = reinterpret_cast<const float4*>(x) + (size_t)rl * 2;
    float4 a = xp[0];
    float4 d = xp[1];

    // W/bias -> shared, in flight during the cos math below.
    if (tid <= NFEAT) {
        float lo, hi;
        if (tid < NFEAT) { lo = W[tid];  hi = W[NFEAT + tid]; }
        else             { lo = bias[0]; hi = bias[1]; }
        sW[tid] = pack2(lo, hi);
    }

    // 8 scalar cosines, duplicated into both f32x2 lanes.
    uint64_t cd[NQ];
    cd[0] = pack_dup(cos_poly(a.x));
    cd[1] = pack_dup(cos_poly(a.y));
    cd[2] = pack_dup(cos_poly(a.z));
    cd[3] = pack_dup(cos_poly(a.w));
    cd[4] = pack_dup(cos_poly(d.x));
    cd[5] = pack_dup(cos_poly(d.y));
    cd[6] = pack_dup(cos_poly(d.z));
    cd[7] = pack_dup(cos_poly(d.w));

    __syncthreads();

    uint32_t sbase = (uint32_t)__cvta_generic_to_shared(sW);

    uint64_t acc0 = lds64(sbase + NFEAT * 8);  // bias pair
    uint64_t acc1 = 0ull;

    // Single-Z chain (ranges starting at q=0, weights sW[0..7]):
    //   sum_k u_k * prod_{q=0..k} c_q = c0*(u0 + c1*(u1 + ... c7*(u7)))
    {
        uint64_t h = lds64(sbase + 7 * 8);
#pragma unroll
        for (int k = 6; k >= 0; k--)
            h = fma2(cd[k + 1], h, lds64(sbase + k * 8));
        acc1 = fma2(cd[0], h, acc1);   // longest chain -> acc1 (bias on acc0)
    }

    // Pair chains: for each i, features (i,j) = prod_{q=i+1..j} c_q,
    // weights at f = 8 + i*7 - i*(i-1)/2 + (j-i-1).
#pragma unroll
    for (int i = 0; i < NQ - 1; i++) {
        const int off = 8 + i * 7 - (i * (i - 1)) / 2;
        uint64_t h = lds64(sbase + (off + 6 - i) * 8);   // w(i,7)
#pragma unroll
        for (int j = 6; j >= i + 1; j--)
            h = fma2(cd[j + 1], h, lds64(sbase + (off + j - i - 1) * 8));
        if (i & 1) acc1 = fma2(cd[i + 1], h, acc1);
        else       acc0 = fma2(cd[i + 1], h, acc0);
    }

    uint64_t r = add2(acc0, acc1);
    if (!GUARDED || row < nrows)
        reinterpret_cast<uint64_t*>(out)[row] = r;
}

__global__ void __launch_bounds__(BLOCK)
quantum_parity_kernel(const float* __restrict__ x,
                      const float* __restrict__ W,
                      const float* __restrict__ bias,
                      float* __restrict__ out) {
    body<false>(x, W, bias, out, 0);
}

__global__ void __launch_bounds__(BLOCK)
quantum_parity_kernel_guard(const float* __restrict__ x,
                            const float* __restrict__ W,
                            const float* __restrict__ bias,
                            float* __restrict__ out, int nrows) {
    body<true>(x, W, bias, out, nrows);
}

extern "C" void kernel_launch(void* const* d_in, const int* in_sizes, int n_in,
                              void* d_out, int out_size) {
    const float* x    = (const float*)d_in[0];   // (B, 8) fp32
    const float* W    = (const float*)d_in[1];   // (2, 36) fp32
    const float* bias = (const float*)d_in[2];   // (2,) fp32

    int nrows = in_sizes[0] / NQ;                // 131072
    float* out = (float*)d_out;                  // (B, 2) fp32

    if (nrows % BLOCK == 0) {
        quantum_parity_kernel<<<nrows / BLOCK, BLOCK>>>(x, W, bias, out);
    } else {
        int grid = (nrows + BLOCK - 1) / BLOCK;
        quantum_parity_kernel_guard<<<grid, BLOCK>>>(x, W, bias, out, nrows);
    }
}

// round 13
// speedup vs baseline: 1.0388x; 1.0388x over previous
#include <cuda_runtime.h>
#include <cstdint>

// QuantumParity analytic reduction (derived R1):
//   The circuit's 36 features are Heisenberg-evolved parity expectations of
//   a product state; every feature is a contiguous-range cosine product:
//     feat_k     = prod_{q=0..k}   cos(x_q)        (k = 0..7)
//     feat_(i,j) = prod_{q=i+1..j} cos(x_q)        (i<j, 28 pairs)
//   out[c] = b[c] + sum_f W[c][f] * feat_f
//
// FINAL (== R9, best measured: bench 6.656us, kernel 5.184us):
//   - scalar degree-9 cos (|err| < 2.8e-6)
//   - smem W (packed {W0,W1} per 64-bit slot) fetched in flight under the
//     cos math; single __syncthreads
//   - Horner-factored packed f32x2 dot: exactly 37 fma2 + 37 LDS.64
//     (all 28 window-product muls eliminated)
//   - 1 row/thread, block 256, single kernel node
// Kernel sits at the small-transfer floor: 5.25MB compulsory-miss traffic,
// all pipes <14%; duration = launch ramp + cold DRAM latency.

#define NQ 8
#define NFEAT 36

__device__ __forceinline__ uint64_t pack2(float lo, float hi) {
    uint64_t r;
    asm("mov.b64 %0, {%1, %2};" : "=l"(r) : "f"(lo), "f"(hi));
    return r;
}
__device__ __forceinline__ uint64_t pack_dup(float v) {
    uint64_t r;
    asm("mov.b64 %0, {%1, %1};" : "=l"(r) : "f"(v));
    return r;
}
__device__ __forceinline__ uint64_t fma2(uint64_t a, uint64_t b, uint64_t c) {
    uint64_t d;
    asm("fma.rn.f32x2 %0, %1, %2, %3;" : "=l"(d) : "l"(a), "l"(b), "l"(c));
    return d;
}
__device__ __forceinline__ uint64_t add2(uint64_t a, uint64_t b) {
    uint64_t d;
    asm("add.rn.f32x2 %0, %1, %2;" : "=l"(d) : "l"(a), "l"(b));
    return d;
}
__device__ __forceinline__ uint64_t lds64(uint32_t addr) {
    uint64_t d;
    asm("ld.shared.b64 %0, [%1];" : "=l"(d) : "r"(addr));
    return d;
}

__device__ __forceinline__ float cos_poly(float x) {
    // x in [0, pi]; cos(x) = -sin(x - pi/2). Degree-9 Taylor, |err| < 2.8e-6.
    float t = x - 1.57079632679489662f;
    float u = t * t;
    float p = fmaf(u, 2.75573192e-6f, -1.98412698e-4f);
    p = fmaf(u, p, 8.33333333e-3f);
    p = fmaf(u, p, -1.66666667e-1f);
    p = fmaf(u, p, 1.0f);
    return -t * p;
}

__global__ void __launch_bounds__(256)
quantum_parity_kernel(const float* __restrict__ x,
                      const float* __restrict__ W,
                      const float* __restrict__ bias,
                      float* __restrict__ out,
                      int nrows) {
    __shared__ uint64_t sW[NFEAT + 1];  // sW[f] = {W0[f], W1[f]}; sW[36] = bias
    int tid = threadIdx.x;
    int row = blockIdx.x * 256 + tid;
    int rl = row < nrows ? row : (nrows - 1);

    // x load first: DRAM latency starts immediately.
    const float4* xp = reinterpret_cast<const float4*>(x) + (size_t)rl * 2;
    float4 a = xp[0];
    float4 d = xp[1];

    // W/bias -> shared, in flight during the cos math below.
    if (tid <= NFEAT) {
        float lo, hi;
        if (tid < NFEAT) { lo = W[tid];  hi = W[NFEAT + tid]; }
        else             { lo = bias[0]; hi = bias[1]; }
        sW[tid] = pack2(lo, hi);
    }

    // 8 scalar cosines, duplicated into both f32x2 lanes.
    uint64_t cd[NQ];
    cd[0] = pack_dup(cos_poly(a.x));
    cd[1] = pack_dup(cos_poly(a.y));
    cd[2] = pack_dup(cos_poly(a.z));
    cd[3] = pack_dup(cos_poly(a.w));
    cd[4] = pack_dup(cos_poly(d.x));
    cd[5] = pack_dup(cos_poly(d.y));
    cd[6] = pack_dup(cos_poly(d.z));
    cd[7] = pack_dup(cos_poly(d.w));

    __syncthreads();

    uint32_t sbase = (uint32_t)__cvta_generic_to_shared(sW);

    uint64_t acc0 = lds64(sbase + NFEAT * 8);  // bias pair
    uint64_t acc1 = 0ull;

    // Single-Z chain (ranges starting at q=0, weights sW[0..7]):
    //   sum_k u_k * prod_{q=0..k} c_q = c0*(u0 + c1*(u1 + ... c7*(u7)))
    {
        uint64_t h = lds64(sbase + 7 * 8);
#pragma unroll
        for (int k = 6; k >= 0; k--)
            h = fma2(cd[k + 1], h, lds64(sbase + k * 8));
        acc0 = fma2(cd[0], h, acc0);
    }

    // Pair chains: for each i, features (i,j) = prod_{q=i+1..j} c_q,
    // weights at f = 8 + i*7 - i*(i-1)/2 + (j-i-1).
#pragma unroll
    for (int i = 0; i < NQ - 1; i++) {
        const int off = 8 + i * 7 - (i * (i - 1)) / 2;
        uint64_t h = lds64(sbase + (off + 6 - i) * 8);   // w(i,7)
#pragma unroll
        for (int j = 6; j >= i + 1; j--)
            h = fma2(cd[j + 1], h, lds64(sbase + (off + j - i - 1) * 8));
        if (i & 1) acc1 = fma2(cd[i + 1], h, acc1);
        else       acc0 = fma2(cd[i + 1], h, acc0);
    }

    if (row < nrows)
        reinterpret_cast<uint64_t*>(out)[row] = add2(acc0, acc1);
}

extern "C" void kernel_launch(void* const* d_in, const int* in_sizes, int n_in,
                              void* d_out, int out_size) {
    const float* x    = (const float*)d_in[0];   // (B, 8) fp32
    const float* W    = (const float*)d_in[1];   // (2, 36) fp32
    const float* bias = (const float*)d_in[2];   // (2,) fp32

    int nrows = in_sizes[0] / NQ;                // 131072
    float* out = (float*)d_out;                  // (B, 2) fp32

    int block = 256;
    int grid = (nrows + block - 1) / block;      // 512
    quantum_parity_kernel<<<grid, block>>>(x, W, bias, out, nrows);
}